// round 1
// baseline (speedup 1.0000x reference)
#include <cuda_runtime.h>
#include <math.h>

// ---------------------------------------------------------------------------
// BatchHardTripletLoss on GB300 — Round 1: correct fp32 streaming baseline.
//
// Structure:
//   1) normalize_k : normed = emb / max(||emb||, 1e-12)           (O(N*D))
//   2) hp_k        : hardest positive per anchor (same-pid only)  (cheap)
//   3) main_k      : streaming N x N sim pass, fused masked maxes (17.2 GMAC)
//   4) finish_k    : scalar mean over valid anchors
// ---------------------------------------------------------------------------

#define MAXN 8192
#define MAXD 256

__device__ float g_normed[MAXN * MAXD];
__device__ float g_hp[MAXN];
__device__ float g_loss[MAXN];
__device__ float g_validf[MAXN];

// ------------------------------- normalize --------------------------------
__global__ void normalize_k(const float* __restrict__ emb, int N, int D) {
    int i = blockIdx.x;
    const float* row = emb + (size_t)i * D;
    float ss = 0.f;
    for (int k = threadIdx.x; k < D; k += blockDim.x) {
        float v = row[k];
        ss += v * v;
    }
    __shared__ float red[32];
    for (int o = 16; o; o >>= 1) ss += __shfl_xor_sync(0xffffffffu, ss, o);
    int wid = threadIdx.x >> 5, lane = threadIdx.x & 31;
    if (lane == 0) red[wid] = ss;
    __syncthreads();
    int nw = (blockDim.x + 31) >> 5;
    if (wid == 0) {
        float v = lane < nw ? red[lane] : 0.f;
        for (int o = 16; o; o >>= 1) v += __shfl_xor_sync(0xffffffffu, v, o);
        if (lane == 0) red[0] = v;
    }
    __syncthreads();
    float inv = 1.0f / fmaxf(sqrtf(red[0]), 1e-12f);
    for (int k = threadIdx.x; k < D; k += blockDim.x)
        g_normed[(size_t)i * D + k] = row[k] * inv;
}

// ----------------------- hardest positive (per anchor) --------------------
// One warp per anchor. Positives only exist within the same pid (~32/8192),
// so we scan pids with a ballot and only run dot products on matches.
__global__ void hp_k(const int* __restrict__ labels, const int* __restrict__ pids,
                     int N, int D) {
    int gw = (blockIdx.x * blockDim.x + threadIdx.x) >> 5;
    int lane = threadIdx.x & 31;
    if (gw >= N) return;
    int i = gw;
    int mypid = pids[i];
    int DK = D >> 5;  // floats per lane (D assumed multiple of 32, <= 256)
    float a[8];
#pragma unroll
    for (int k = 0; k < 8; k++)
        a[k] = (k < DK) ? g_normed[(size_t)i * D + k * 32 + lane] : 0.f;

    float hp = 1e9f;
    for (int jb = 0; jb < N; jb += 32) {
        int j = jb + lane;
        bool m = (pids[j] == mypid) && (labels[j] == 1) && (j != i);
        unsigned bal = __ballot_sync(0xffffffffu, m);
        while (bal) {
            int b = __ffs(bal) - 1;
            bal &= bal - 1;
            int jj = jb + b;
            float s = 0.f;
#pragma unroll
            for (int k = 0; k < 8; k++)
                if (k < DK) s += a[k] * g_normed[(size_t)jj * D + k * 32 + lane];
            for (int o = 16; o; o >>= 1) s += __shfl_xor_sync(0xffffffffu, s, o);
            hp = fminf(hp, s);
        }
    }
    if (lane == 0) g_hp[i] = hp;
}

// ------------------------------- main pass --------------------------------
// Block tile: TM=64 rows x TN=128 cols. 256 threads, each owns a 4x8 register
// tile. Smem in [k][row] transposed layout (padded) -> conflict-free float4
// reads in the inner product loop. Running hn_semi/hn_cand/hn_all maxes are
// kept in registers across all column tiles; hp comes from the pre-pass.
#define TM 64
#define TN 128
#define KC 32

__global__ void __launch_bounds__(256, 1)
main_k(const int* __restrict__ labels, const int* __restrict__ pids, int N, int D) {
    __shared__ float As[KC][TM + 4];
    __shared__ float Bs[KC][TN + 4];
    __shared__ int s_pid[TN];
    __shared__ int s_lab[TN];

    int tid = threadIdx.x;
    int tx = tid & 15;   // column group: cols tx*8 .. tx*8+7
    int ty = tid >> 4;   // row group:    rows ty*4 .. ty*4+3
    int row0 = blockIdx.x * TM;

    float hp_r[4];
    int pid_r[4];
#pragma unroll
    for (int r = 0; r < 4; r++) {
        int i = row0 + ty * 4 + r;
        hp_r[r] = g_hp[i];
        pid_r[r] = pids[i];
    }

    float hs[4], hc[4], ha[4];
#pragma unroll
    for (int r = 0; r < 4; r++) { hs[r] = -1e9f; hc[r] = -1e9f; ha[r] = -1e9f; }

    for (int jt = 0; jt < N; jt += TN) {
        __syncthreads();  // previous epilogue done with s_pid/s_lab
        if (tid < TN) {
            s_pid[tid] = pids[jt + tid];
            s_lab[tid] = labels[jt + tid];
        }

        float acc[4][8];
#pragma unroll
        for (int r = 0; r < 4; r++)
#pragma unroll
            for (int c = 0; c < 8; c++) acc[r][c] = 0.f;

        for (int kk = 0; kk < D; kk += KC) {
            __syncthreads();
            // fill As: TM x KC = 512 float4, 2 per thread (coalesced global)
#pragma unroll
            for (int it = 0; it < 2; it++) {
                int f = tid + it * 256;
                int r = f >> 3;
                int kq = f & 7;
                float4 v = *(const float4*)&g_normed[(size_t)(row0 + r) * D + kk + kq * 4];
                As[kq * 4 + 0][r] = v.x;
                As[kq * 4 + 1][r] = v.y;
                As[kq * 4 + 2][r] = v.z;
                As[kq * 4 + 3][r] = v.w;
            }
            // fill Bs: TN x KC = 1024 float4, 4 per thread
#pragma unroll
            for (int it = 0; it < 4; it++) {
                int f = tid + it * 256;
                int r = f >> 3;
                int kq = f & 7;
                float4 v = *(const float4*)&g_normed[(size_t)(jt + r) * D + kk + kq * 4];
                Bs[kq * 4 + 0][r] = v.x;
                Bs[kq * 4 + 1][r] = v.y;
                Bs[kq * 4 + 2][r] = v.z;
                Bs[kq * 4 + 3][r] = v.w;
            }
            __syncthreads();
#pragma unroll
            for (int k = 0; k < KC; k++) {
                float4 a4 = *(const float4*)&As[k][ty * 4];
                float4 b0 = *(const float4*)&Bs[k][tx * 8];
                float4 b1 = *(const float4*)&Bs[k][tx * 8 + 4];
                float av[4] = {a4.x, a4.y, a4.z, a4.w};
                float bv[8] = {b0.x, b0.y, b0.z, b0.w, b1.x, b1.y, b1.z, b1.w};
#pragma unroll
                for (int r = 0; r < 4; r++)
#pragma unroll
                    for (int c = 0; c < 8; c++)
                        acc[r][c] = fmaf(av[r], bv[c], acc[r][c]);
            }
        }

        // epilogue: fold this 64x128 sim tile into running masked maxes
#pragma unroll
        for (int c = 0; c < 8; c++) {
            int jl = tx * 8 + c;
            int pj = s_pid[jl];
            int lj = s_lab[jl];
#pragma unroll
            for (int r = 0; r < 4; r++) {
                bool neg = !((pj == pid_r[r]) && (lj == 1));  // neg = ~(same_pid & genuine_j)
                if (neg) {
                    float s = acc[r][c];
                    float hp = hp_r[r];
                    ha[r] = fmaxf(ha[r], s);
                    if (s > hp)
                        hc[r] = fmaxf(hc[r], s);
                    else if (s > hp - 0.5f && s < hp)
                        hs[r] = fmaxf(hs[r], s);
                }
            }
        }
    }

    // reduce the 16 column-group partials per row (16-lane subgroups)
#pragma unroll
    for (int r = 0; r < 4; r++) {
        for (int o = 8; o; o >>= 1) {
            hs[r] = fmaxf(hs[r], __shfl_xor_sync(0xffffffffu, hs[r], o, 16));
            hc[r] = fmaxf(hc[r], __shfl_xor_sync(0xffffffffu, hc[r], o, 16));
            ha[r] = fmaxf(ha[r], __shfl_xor_sync(0xffffffffu, ha[r], o, 16));
        }
    }

    if (tx == 0) {
#pragma unroll
        for (int r = 0; r < 4; r++) {
            int i = row0 + ty * 4 + r;
            float hp = hp_r[r];
            float hn = (hs[r] > -1e8f) ? hs[r] : ((hc[r] > -1e8f) ? hc[r] : ha[r]);
            float base = fmaxf(hn - hp + 0.5f, 0.f);
            float w = (hp < 0.6f || hn > 0.3f) ? 2.0f : 1.0f;
            float loss = base * w + 0.5f * (1.0f - hp) + 0.5f * fmaxf(hn + 0.2f, 0.f);
            bool valid = (labels[i] == 1) && (hp < 1e8f) && (ha[r] > -1e8f);
            g_loss[i] = valid ? loss : 0.f;
            g_validf[i] = valid ? 1.f : 0.f;
        }
    }
}

// ------------------------------ final reduce ------------------------------
__global__ void finish_k(float* __restrict__ out, int N) {
    double s = 0.0, c = 0.0;
    for (int i = threadIdx.x; i < N; i += blockDim.x) {
        s += (double)g_loss[i];
        c += (double)g_validf[i];
    }
    __shared__ double rs[32], rc[32];
    for (int o = 16; o; o >>= 1) {
        s += __shfl_xor_sync(0xffffffffu, s, o);
        c += __shfl_xor_sync(0xffffffffu, c, o);
    }
    int wid = threadIdx.x >> 5, lane = threadIdx.x & 31;
    if (lane == 0) { rs[wid] = s; rc[wid] = c; }
    __syncthreads();
    int nw = (blockDim.x + 31) >> 5;
    if (wid == 0) {
        double vs = lane < nw ? rs[lane] : 0.0;
        double vc = lane < nw ? rc[lane] : 0.0;
        for (int o = 16; o; o >>= 1) {
            vs += __shfl_xor_sync(0xffffffffu, vs, o);
            vc += __shfl_xor_sync(0xffffffffu, vc, o);
        }
        if (lane == 0) out[0] = (vc > 0.0) ? (float)(vs / vc) : 0.f;
    }
}

// ------------------------------- launcher ---------------------------------
extern "C" void kernel_launch(void* const* d_in, const int* in_sizes, int n_in,
                              void* d_out, int out_size) {
    const float* emb = (const float*)d_in[0];
    const int* labels = (const int*)d_in[1];
    const int* pids = (const int*)d_in[2];
    float* out = (float*)d_out;

    int N = in_sizes[1];
    int D = in_sizes[0] / N;

    normalize_k<<<N, 256>>>(emb, N, D);
    hp_k<<<(N * 32 + 255) / 256, 256>>>(labels, pids, N, D);
    main_k<<<N / TM, 256>>>(labels, pids, N, D);
    finish_k<<<1, 1024>>>(out, N);
}

// round 2
// speedup vs baseline: 1.0023x; 1.0023x over previous
#include <cuda_runtime.h>
#include <math.h>

// ---------------------------------------------------------------------------
// BatchHardTripletLoss on GB300 — Round 1: correct fp32 streaming baseline.
//
// Structure:
//   1) normalize_k : normed = emb / max(||emb||, 1e-12)           (O(N*D))
//   2) hp_k        : hardest positive per anchor (same-pid only)  (cheap)
//   3) main_k      : streaming N x N sim pass, fused masked maxes (17.2 GMAC)
//   4) finish_k    : scalar mean over valid anchors
// ---------------------------------------------------------------------------

#define MAXN 8192
#define MAXD 256

__device__ float g_normed[MAXN * MAXD];
__device__ float g_hp[MAXN];
__device__ float g_loss[MAXN];
__device__ float g_validf[MAXN];

// ------------------------------- normalize --------------------------------
__global__ void normalize_k(const float* __restrict__ emb, int N, int D) {
    int i = blockIdx.x;
    const float* row = emb + (size_t)i * D;
    float ss = 0.f;
    for (int k = threadIdx.x; k < D; k += blockDim.x) {
        float v = row[k];
        ss += v * v;
    }
    __shared__ float red[32];
    for (int o = 16; o; o >>= 1) ss += __shfl_xor_sync(0xffffffffu, ss, o);
    int wid = threadIdx.x >> 5, lane = threadIdx.x & 31;
    if (lane == 0) red[wid] = ss;
    __syncthreads();
    int nw = (blockDim.x + 31) >> 5;
    if (wid == 0) {
        float v = lane < nw ? red[lane] : 0.f;
        for (int o = 16; o; o >>= 1) v += __shfl_xor_sync(0xffffffffu, v, o);
        if (lane == 0) red[0] = v;
    }
    __syncthreads();
    float inv = 1.0f / fmaxf(sqrtf(red[0]), 1e-12f);
    for (int k = threadIdx.x; k < D; k += blockDim.x)
        g_normed[(size_t)i * D + k] = row[k] * inv;
}

// ----------------------- hardest positive (per anchor) --------------------
// One warp per anchor. Positives only exist within the same pid (~32/8192),
// so we scan pids with a ballot and only run dot products on matches.
__global__ void hp_k(const int* __restrict__ labels, const int* __restrict__ pids,
                     int N, int D) {
    int gw = (blockIdx.x * blockDim.x + threadIdx.x) >> 5;
    int lane = threadIdx.x & 31;
    if (gw >= N) return;
    int i = gw;
    int mypid = pids[i];
    int DK = D >> 5;  // floats per lane (D assumed multiple of 32, <= 256)
    float a[8];
#pragma unroll
    for (int k = 0; k < 8; k++)
        a[k] = (k < DK) ? g_normed[(size_t)i * D + k * 32 + lane] : 0.f;

    float hp = 1e9f;
    for (int jb = 0; jb < N; jb += 32) {
        int j = jb + lane;
        bool m = (pids[j] == mypid) && (labels[j] == 1) && (j != i);
        unsigned bal = __ballot_sync(0xffffffffu, m);
        while (bal) {
            int b = __ffs(bal) - 1;
            bal &= bal - 1;
            int jj = jb + b;
            float s = 0.f;
#pragma unroll
            for (int k = 0; k < 8; k++)
                if (k < DK) s += a[k] * g_normed[(size_t)jj * D + k * 32 + lane];
            for (int o = 16; o; o >>= 1) s += __shfl_xor_sync(0xffffffffu, s, o);
            hp = fminf(hp, s);
        }
    }
    if (lane == 0) g_hp[i] = hp;
}

// ------------------------------- main pass --------------------------------
// Block tile: TM=64 rows x TN=128 cols. 256 threads, each owns a 4x8 register
// tile. Smem in [k][row] transposed layout (padded) -> conflict-free float4
// reads in the inner product loop. Running hn_semi/hn_cand/hn_all maxes are
// kept in registers across all column tiles; hp comes from the pre-pass.
#define TM 64
#define TN 128
#define KC 32

__global__ void __launch_bounds__(256, 1)
main_k(const int* __restrict__ labels, const int* __restrict__ pids, int N, int D) {
    __shared__ float As[KC][TM + 4];
    __shared__ float Bs[KC][TN + 4];
    __shared__ int s_pid[TN];
    __shared__ int s_lab[TN];

    int tid = threadIdx.x;
    int tx = tid & 15;   // column group: cols tx*8 .. tx*8+7
    int ty = tid >> 4;   // row group:    rows ty*4 .. ty*4+3
    int row0 = blockIdx.x * TM;

    float hp_r[4];
    int pid_r[4];
#pragma unroll
    for (int r = 0; r < 4; r++) {
        int i = row0 + ty * 4 + r;
        hp_r[r] = g_hp[i];
        pid_r[r] = pids[i];
    }

    float hs[4], hc[4], ha[4];
#pragma unroll
    for (int r = 0; r < 4; r++) { hs[r] = -1e9f; hc[r] = -1e9f; ha[r] = -1e9f; }

    for (int jt = 0; jt < N; jt += TN) {
        __syncthreads();  // previous epilogue done with s_pid/s_lab
        if (tid < TN) {
            s_pid[tid] = pids[jt + tid];
            s_lab[tid] = labels[jt + tid];
        }

        float acc[4][8];
#pragma unroll
        for (int r = 0; r < 4; r++)
#pragma unroll
            for (int c = 0; c < 8; c++) acc[r][c] = 0.f;

        for (int kk = 0; kk < D; kk += KC) {
            __syncthreads();
            // fill As: TM x KC = 512 float4, 2 per thread (coalesced global)
#pragma unroll
            for (int it = 0; it < 2; it++) {
                int f = tid + it * 256;
                int r = f >> 3;
                int kq = f & 7;
                float4 v = *(const float4*)&g_normed[(size_t)(row0 + r) * D + kk + kq * 4];
                As[kq * 4 + 0][r] = v.x;
                As[kq * 4 + 1][r] = v.y;
                As[kq * 4 + 2][r] = v.z;
                As[kq * 4 + 3][r] = v.w;
            }
            // fill Bs: TN x KC = 1024 float4, 4 per thread
#pragma unroll
            for (int it = 0; it < 4; it++) {
                int f = tid + it * 256;
                int r = f >> 3;
                int kq = f & 7;
                float4 v = *(const float4*)&g_normed[(size_t)(jt + r) * D + kk + kq * 4];
                Bs[kq * 4 + 0][r] = v.x;
                Bs[kq * 4 + 1][r] = v.y;
                Bs[kq * 4 + 2][r] = v.z;
                Bs[kq * 4 + 3][r] = v.w;
            }
            __syncthreads();
#pragma unroll
            for (int k = 0; k < KC; k++) {
                float4 a4 = *(const float4*)&As[k][ty * 4];
                float4 b0 = *(const float4*)&Bs[k][tx * 8];
                float4 b1 = *(const float4*)&Bs[k][tx * 8 + 4];
                float av[4] = {a4.x, a4.y, a4.z, a4.w};
                float bv[8] = {b0.x, b0.y, b0.z, b0.w, b1.x, b1.y, b1.z, b1.w};
#pragma unroll
                for (int r = 0; r < 4; r++)
#pragma unroll
                    for (int c = 0; c < 8; c++)
                        acc[r][c] = fmaf(av[r], bv[c], acc[r][c]);
            }
        }

        // epilogue: fold this 64x128 sim tile into running masked maxes
#pragma unroll
        for (int c = 0; c < 8; c++) {
            int jl = tx * 8 + c;
            int pj = s_pid[jl];
            int lj = s_lab[jl];
#pragma unroll
            for (int r = 0; r < 4; r++) {
                bool neg = !((pj == pid_r[r]) && (lj == 1));  // neg = ~(same_pid & genuine_j)
                if (neg) {
                    float s = acc[r][c];
                    float hp = hp_r[r];
                    ha[r] = fmaxf(ha[r], s);
                    if (s > hp)
                        hc[r] = fmaxf(hc[r], s);
                    else if (s > hp - 0.5f && s < hp)
                        hs[r] = fmaxf(hs[r], s);
                }
            }
        }
    }

    // reduce the 16 column-group partials per row (16-lane subgroups)
#pragma unroll
    for (int r = 0; r < 4; r++) {
        for (int o = 8; o; o >>= 1) {
            hs[r] = fmaxf(hs[r], __shfl_xor_sync(0xffffffffu, hs[r], o, 16));
            hc[r] = fmaxf(hc[r], __shfl_xor_sync(0xffffffffu, hc[r], o, 16));
            ha[r] = fmaxf(ha[r], __shfl_xor_sync(0xffffffffu, ha[r], o, 16));
        }
    }

    if (tx == 0) {
#pragma unroll
        for (int r = 0; r < 4; r++) {
            int i = row0 + ty * 4 + r;
            float hp = hp_r[r];
            float hn = (hs[r] > -1e8f) ? hs[r] : ((hc[r] > -1e8f) ? hc[r] : ha[r]);
            float base = fmaxf(hn - hp + 0.5f, 0.f);
            float w = (hp < 0.6f || hn > 0.3f) ? 2.0f : 1.0f;
            float loss = base * w + 0.5f * (1.0f - hp) + 0.5f * fmaxf(hn + 0.2f, 0.f);
            bool valid = (labels[i] == 1) && (hp < 1e8f) && (ha[r] > -1e8f);
            g_loss[i] = valid ? loss : 0.f;
            g_validf[i] = valid ? 1.f : 0.f;
        }
    }
}

// ------------------------------ final reduce ------------------------------
__global__ void finish_k(float* __restrict__ out, int N) {
    double s = 0.0, c = 0.0;
    for (int i = threadIdx.x; i < N; i += blockDim.x) {
        s += (double)g_loss[i];
        c += (double)g_validf[i];
    }
    __shared__ double rs[32], rc[32];
    for (int o = 16; o; o >>= 1) {
        s += __shfl_xor_sync(0xffffffffu, s, o);
        c += __shfl_xor_sync(0xffffffffu, c, o);
    }
    int wid = threadIdx.x >> 5, lane = threadIdx.x & 31;
    if (lane == 0) { rs[wid] = s; rc[wid] = c; }
    __syncthreads();
    int nw = (blockDim.x + 31) >> 5;
    if (wid == 0) {
        double vs = lane < nw ? rs[lane] : 0.0;
        double vc = lane < nw ? rc[lane] : 0.0;
        for (int o = 16; o; o >>= 1) {
            vs += __shfl_xor_sync(0xffffffffu, vs, o);
            vc += __shfl_xor_sync(0xffffffffu, vc, o);
        }
        if (lane == 0) out[0] = (vc > 0.0) ? (float)(vs / vc) : 0.f;
    }
}

// ------------------------------- launcher ---------------------------------
extern "C" void kernel_launch(void* const* d_in, const int* in_sizes, int n_in,
                              void* d_out, int out_size) {
    const float* emb = (const float*)d_in[0];
    const int* labels = (const int*)d_in[1];
    const int* pids = (const int*)d_in[2];
    float* out = (float*)d_out;

    int N = in_sizes[1];
    int D = in_sizes[0] / N;

    normalize_k<<<N, 256>>>(emb, N, D);
    hp_k<<<(N * 32 + 255) / 256, 256>>>(labels, pids, N, D);
    main_k<<<N / TM, 256>>>(labels, pids, N, D);
    finish_k<<<1, 1024>>>(out, N);
}

// round 4
// speedup vs baseline: 9.0242x; 9.0035x over previous
#include <cuda_runtime.h>
#include <cuda_fp16.h>
#include <cstdint>
#include <math.h>

#define N_    8192
#define D_    256
#define NPID  256
#define CAP   8192
#define NTILE 32    // column tiles per CTA (4096/128)

__device__ float  g_normed[N_ * D_];
__device__ __half g_nh[N_ * D_];
__device__ float  g_hp[N_];
__device__ float  g_validf[N_];
__device__ int    g_colsent[N_];
__device__ int    g_cnt[NPID];
__device__ int    g_list[NPID * CAP];
__device__ unsigned g_hsE[N_], g_hcE[N_], g_haE[N_];

// monotone float <-> uint map (for atomicMax on floats incl. negatives)
__device__ __forceinline__ unsigned encf(float f) {
    unsigned u = __float_as_uint(f);
    return (u & 0x80000000u) ? ~u : (u | 0x80000000u);
}
__device__ __forceinline__ float decf(unsigned e) {
    unsigned u = (e & 0x80000000u) ? (e ^ 0x80000000u) : ~e;
    return __uint_as_float(u);
}

__device__ __forceinline__ uint32_t smem_u32(const void* p) {
    uint32_t a;
    asm("{ .reg .u64 t; cvta.to.shared.u64 t, %1; cvt.u32.u64 %0, t; }" : "=r"(a) : "l"(p));
    return a;
}
__device__ __forceinline__ void cpa16(uint32_t d, const void* s) {
    asm volatile("cp.async.cg.shared.global [%0], [%1], 16;" :: "r"(d), "l"(s) : "memory");
}
#define CP_COMMIT() asm volatile("cp.async.commit_group;" ::: "memory")
#define CP_WAIT(n)  asm volatile("cp.async.wait_group %0;" :: "n"(n) : "memory")

__device__ __forceinline__ void ldsm4(uint32_t& r0, uint32_t& r1, uint32_t& r2, uint32_t& r3,
                                      uint32_t addr) {
    asm volatile("ldmatrix.sync.aligned.m8n8.x4.shared.b16 {%0,%1,%2,%3}, [%4];"
                 : "=r"(r0), "=r"(r1), "=r"(r2), "=r"(r3) : "r"(addr));
}
__device__ __forceinline__ void mma16816(float& c0, float& c1, float& c2, float& c3,
                                         uint32_t a0, uint32_t a1, uint32_t a2, uint32_t a3,
                                         uint32_t b0, uint32_t b1) {
    asm volatile("mma.sync.aligned.m16n8k16.row.col.f32.f16.f16.f32 "
                 "{%0,%1,%2,%3},{%4,%5,%6,%7},{%8,%9},{%0,%1,%2,%3};"
                 : "+f"(c0), "+f"(c1), "+f"(c2), "+f"(c3)
                 : "r"(a0), "r"(a1), "r"(a2), "r"(a3), "r"(b0), "r"(b1));
}

// ---------------- init ----------------
__global__ void init_k() {
    int i = blockIdx.x * blockDim.x + threadIdx.x;
    if (i < N_) {
        unsigned e = encf(-1e9f);
        g_hsE[i] = e; g_hcE[i] = e; g_haE[i] = e;
    }
    if (i < NPID) g_cnt[i] = 0;
}

// ---------------- normalize (fp32 + fp16 copies) ----------------
__global__ void normalize_k(const float* __restrict__ emb) {
    int j = blockIdx.x, t = threadIdx.x;  // 64 threads, one float4 each
    float4 v = ((const float4*)(emb + (size_t)j * D_))[t];
    float ss = v.x * v.x + v.y * v.y + v.z * v.z + v.w * v.w;
    for (int o = 16; o; o >>= 1) ss += __shfl_xor_sync(0xffffffffu, ss, o);
    __shared__ float sred[2];
    if ((t & 31) == 0) sred[t >> 5] = ss;
    __syncthreads();
    float inv = 1.0f / fmaxf(sqrtf(sred[0] + sred[1]), 1e-12f);
    float4 o4 = make_float4(v.x * inv, v.y * inv, v.z * inv, v.w * inv);
    ((float4*)(g_normed + (size_t)j * D_))[t] = o4;
    __half2 h0 = __floats2half2_rn(o4.x, o4.y);
    __half2 h1 = __floats2half2_rn(o4.z, o4.w);
    ((__half2*)(g_nh + (size_t)j * D_ + t * 4))[0] = h0;
    ((__half2*)(g_nh + (size_t)j * D_ + t * 4))[1] = h1;
}

// ---------------- pid buckets + column sentinels ----------------
__global__ void bucket_k(const int* __restrict__ labels, const int* __restrict__ pids) {
    int i = blockIdx.x * blockDim.x + threadIdx.x;
    if (i >= N_) return;
    int lab = labels[i], pid = pids[i];
    g_colsent[i] = (lab == 1) ? pid : -1;
    if (lab == 1) g_list[pid * CAP + atomicAdd(&g_cnt[pid], 1)] = i;
}

// ---------------- exact fp32 hardest positive ----------------
__global__ void hp2_k(const int* __restrict__ labels, const int* __restrict__ pids) {
    int gw = (blockIdx.x * blockDim.x + threadIdx.x) >> 5;
    int lane = threadIdx.x & 31;
    if (gw >= N_) return;
    int i = gw;
    if (labels[i] != 1) {
        if (lane == 0) { g_hp[i] = 1e9f; g_validf[i] = 0.f; }
        return;
    }
    int pid = pids[i], n = g_cnt[pid];
    float a[8];
#pragma unroll
    for (int k = 0; k < 8; k++) a[k] = g_normed[(size_t)i * D_ + k * 32 + lane];
    float hp = 1e9f;
    for (int idx = 0; idx < n; idx++) {
        int j = g_list[pid * CAP + idx];
        if (j == i) continue;
        float s = 0.f;
#pragma unroll
        for (int k = 0; k < 8; k++) s = fmaf(a[k], g_normed[(size_t)j * D_ + k * 32 + lane], s);
        for (int o = 16; o; o >>= 1) s += __shfl_xor_sync(0xffffffffu, s, o);
        hp = fminf(hp, s);
    }
    if (lane == 0) { g_hp[i] = hp; g_validf[i] = (n >= 2) ? 1.f : 0.f; }
}

// ---------------- main: mma.sync fp16 GEMM + fused masked maxes ----------------
// grid (64 rowblocks, 2 col halves), 256 threads = 8 warps (2 row x 4 col),
// warp tile 64x32, CTA tile 128x128, K=256 smem-resident for A,
// B double-buffered 64KB stages via cp.async.
__global__ void __launch_bounds__(256, 1)
main_k(const int* __restrict__ pids) {
    extern __shared__ char sm[];
    uint32_t sb = smem_u32(sm);
    const uint32_t A0 = sb, Bbuf0 = sb + 65536, Bbuf1 = sb + 131072;

    int tid = threadIdx.x, lane = tid & 31, wid = tid >> 5;
    int wr = (wid >> 2) * 64;   // warp row offset in CTA tile
    int wc = (wid & 3) * 32;    // warp col offset in CTA tile
    int row0 = blockIdx.x * 128;
    int col0 = blockIdx.y * 4096;

    // load A (128x256 half, swizzled) and B stage 0
    {
        const __half* gs = g_nh + (size_t)row0 * D_;
#pragma unroll
        for (int i = 0; i < 16; i++) {
            int id = tid + i * 256, r = id >> 5, c = id & 31;
            cpa16(A0 + r * 512 + ((c ^ (r & 7)) << 4), gs + r * 256 + c * 8);
        }
        CP_COMMIT();
    }
    {
        const __half* gs = g_nh + (size_t)col0 * D_;
#pragma unroll
        for (int i = 0; i < 16; i++) {
            int id = tid + i * 256, r = id >> 5, c = id & 31;
            cpa16(Bbuf0 + r * 512 + ((c ^ (r & 7)) << 4), gs + r * 256 + c * 8);
        }
        CP_COMMIT();
    }

    int gid = lane >> 2, tig = lane & 3;
    float hp_s[8];
    int pid_s[8];
    float hs[8], hc[8], ha[8];
#pragma unroll
    for (int m = 0; m < 4; m++) {
        int rA = row0 + wr + m * 16 + gid;
        hp_s[2 * m] = g_hp[rA];         pid_s[2 * m] = pids[rA];
        hp_s[2 * m + 1] = g_hp[rA + 8]; pid_s[2 * m + 1] = pids[rA + 8];
    }
#pragma unroll
    for (int s = 0; s < 8; s++) { hs[s] = -1e9f; hc[s] = -1e9f; ha[s] = -1e9f; }

    // ldmatrix lane geometry
    int arow = lane & 15;              // A: lanes 0-15 rows 0-15, 16-31 repeat
    int kha = lane >> 4;               // A: k-half select
    int brow = ((lane >> 4) & 1) * 8 + (lane & 7);  // B: n-row within 16
    int khb = (lane >> 3) & 1;         // B: k-half select
    int xr = lane & 7;                 // swizzle key (row & 7)
    uint32_t aAddr[4];
#pragma unroll
    for (int m = 0; m < 4; m++) aAddr[m] = A0 + (wr + m * 16 + arow) * 512;

    for (int t = 0; t < NTILE; t++) {
        uint32_t Bc = (t & 1) ? Bbuf1 : Bbuf0;
        if (t + 1 < NTILE) {
            uint32_t Bn = (t & 1) ? Bbuf0 : Bbuf1;
            const __half* gs = g_nh + (size_t)(col0 + (t + 1) * 128) * D_;
#pragma unroll
            for (int i = 0; i < 16; i++) {
                int id = tid + i * 256, r = id >> 5, c = id & 31;
                cpa16(Bn + r * 512 + ((c ^ (r & 7)) << 4), gs + r * 256 + c * 8);
            }
            CP_COMMIT();
            CP_WAIT(1);
        } else {
            CP_WAIT(0);
        }
        __syncthreads();

        uint32_t bAddr0 = Bc + (wc + brow) * 512;
        uint32_t bAddr1 = Bc + (wc + 16 + brow) * 512;

        float acc[4][4][4];
#pragma unroll
        for (int m = 0; m < 4; m++)
#pragma unroll
            for (int n = 0; n < 4; n++)
#pragma unroll
                for (int q = 0; q < 4; q++) acc[m][n][q] = 0.f;

#pragma unroll
        for (int ks = 0; ks < 16; ks++) {
            uint32_t aoff = (uint32_t)(((ks * 2 + kha) ^ xr) << 4);
            uint32_t boff = (uint32_t)(((ks * 2 + khb) ^ xr) << 4);
            uint32_t a[4][4], b[2][4];
#pragma unroll
            for (int m = 0; m < 4; m++)
                ldsm4(a[m][0], a[m][1], a[m][2], a[m][3], aAddr[m] + aoff);
            ldsm4(b[0][0], b[0][1], b[0][2], b[0][3], bAddr0 + boff);
            ldsm4(b[1][0], b[1][1], b[1][2], b[1][3], bAddr1 + boff);
#pragma unroll
            for (int m = 0; m < 4; m++) {
                mma16816(acc[m][0][0], acc[m][0][1], acc[m][0][2], acc[m][0][3],
                         a[m][0], a[m][1], a[m][2], a[m][3], b[0][0], b[0][1]);
                mma16816(acc[m][1][0], acc[m][1][1], acc[m][1][2], acc[m][1][3],
                         a[m][0], a[m][1], a[m][2], a[m][3], b[0][2], b[0][3]);
                mma16816(acc[m][2][0], acc[m][2][1], acc[m][2][2], acc[m][2][3],
                         a[m][0], a[m][1], a[m][2], a[m][3], b[1][0], b[1][1]);
                mma16816(acc[m][3][0], acc[m][3][1], acc[m][3][2], acc[m][3][3],
                         a[m][0], a[m][1], a[m][2], a[m][3], b[1][2], b[1][3]);
            }
        }
        __syncthreads();

        // fold tile into running masked maxes
        int cb = col0 + t * 128 + wc;
#pragma unroll
        for (int n = 0; n < 4; n++) {
            int c0 = cb + n * 8 + tig * 2;
            int s0 = __ldg(&g_colsent[c0]);
            int s1 = __ldg(&g_colsent[c0 + 1]);
#pragma unroll
            for (int m = 0; m < 4; m++) {
#pragma unroll
                for (int h = 0; h < 2; h++) {
                    int slot = 2 * m + h;
                    float hpv = hp_s[slot];
                    int mp = pid_s[slot];
                    float v0 = acc[m][n][h * 2 + 0];
                    float v1 = acc[m][n][h * 2 + 1];
                    if (s0 != mp) {
                        ha[slot] = fmaxf(ha[slot], v0);
                        if (v0 > hpv) hc[slot] = fmaxf(hc[slot], v0);
                        else if (v0 > hpv - 0.5f && v0 < hpv) hs[slot] = fmaxf(hs[slot], v0);
                    }
                    if (s1 != mp) {
                        ha[slot] = fmaxf(ha[slot], v1);
                        if (v1 > hpv) hc[slot] = fmaxf(hc[slot], v1);
                        else if (v1 > hpv - 0.5f && v1 < hpv) hs[slot] = fmaxf(hs[slot], v1);
                    }
                }
            }
        }
    }

    // reduce across the 4 lanes sharing the same rows (tig dimension)
#pragma unroll
    for (int s = 0; s < 8; s++) {
        for (int o = 1; o < 4; o <<= 1) {
            hs[s] = fmaxf(hs[s], __shfl_xor_sync(0xffffffffu, hs[s], o));
            hc[s] = fmaxf(hc[s], __shfl_xor_sync(0xffffffffu, hc[s], o));
            ha[s] = fmaxf(ha[s], __shfl_xor_sync(0xffffffffu, ha[s], o));
        }
    }
    if (tig == 0) {
#pragma unroll
        for (int m = 0; m < 4; m++) {
            int r = row0 + wr + m * 16 + gid;
            atomicMax(&g_hsE[r], encf(hs[2 * m]));
            atomicMax(&g_hcE[r], encf(hc[2 * m]));
            atomicMax(&g_haE[r], encf(ha[2 * m]));
            atomicMax(&g_hsE[r + 8], encf(hs[2 * m + 1]));
            atomicMax(&g_hcE[r + 8], encf(hc[2 * m + 1]));
            atomicMax(&g_haE[r + 8], encf(ha[2 * m + 1]));
        }
    }
}

// ---------------- final reduce ----------------
__global__ void finish_k(float* __restrict__ out) {
    double s = 0.0, c = 0.0;
    for (int i = threadIdx.x; i < N_; i += blockDim.x) {
        if (g_validf[i] > 0.f) {
            float hp = g_hp[i];
            float hsv = decf(g_hsE[i]);
            float hcv = decf(g_hcE[i]);
            float hav = decf(g_haE[i]);
            float hn = (hsv > -1e8f) ? hsv : ((hcv > -1e8f) ? hcv : hav);
            float base = fmaxf(hn - hp + 0.5f, 0.f);
            float w = (hp < 0.6f || hn > 0.3f) ? 2.0f : 1.0f;
            s += (double)(base * w + 0.5f * (1.0f - hp) + 0.5f * fmaxf(hn + 0.2f, 0.f));
            c += 1.0;
        }
    }
    __shared__ double rs[32], rc[32];
    for (int o = 16; o; o >>= 1) {
        s += __shfl_xor_sync(0xffffffffu, s, o);
        c += __shfl_xor_sync(0xffffffffu, c, o);
    }
    int wid = threadIdx.x >> 5, lane = threadIdx.x & 31;
    if (lane == 0) { rs[wid] = s; rc[wid] = c; }
    __syncthreads();
    int nw = (blockDim.x + 31) >> 5;
    if (wid == 0) {
        double vs = lane < nw ? rs[lane] : 0.0;
        double vc = lane < nw ? rc[lane] : 0.0;
        for (int o = 16; o; o >>= 1) {
            vs += __shfl_xor_sync(0xffffffffu, vs, o);
            vc += __shfl_xor_sync(0xffffffffu, vc, o);
        }
        if (lane == 0) out[0] = (vc > 0.0) ? (float)(vs / vc) : 0.f;
    }
}

// ---------------- launcher ----------------
extern "C" void kernel_launch(void* const* d_in, const int* in_sizes, int n_in,
                              void* d_out, int out_size) {
    const float* emb = (const float*)d_in[0];
    const int* labels = (const int*)d_in[1];
    const int* pids = (const int*)d_in[2];
    float* out = (float*)d_out;

    cudaFuncSetAttribute(main_k, cudaFuncAttributeMaxDynamicSharedMemorySize, 196608);

    init_k<<<N_ / 256, 256>>>();
    normalize_k<<<N_, 64>>>(emb);
    bucket_k<<<N_ / 256, 256>>>(labels, pids);
    hp2_k<<<N_ / 8, 256>>>(labels, pids);
    main_k<<<dim3(64, 2), 256, 196608>>>(pids);
    finish_k<<<1, 1024>>>(out);
}

// round 5
// speedup vs baseline: 10.6838x; 1.1839x over previous
#include <cuda_runtime.h>
#include <cuda_fp16.h>
#include <cstdint>
#include <math.h>

#define N_    8192
#define D_    256
#define NPID  256
#define CAP   8192
#define NTILE 32

__device__ float    g_normed[N_ * D_];
__device__ __half   g_nh[N_ * D_];
__device__ float    g_hp[N_];
__device__ float    g_validf[N_];
__device__ int      g_colsent[N_];
__device__ int      g_cnt[NPID];
__device__ int      g_list[NPID * CAP];
__device__ unsigned g_tE[N_];   // encoded running max of class-offset value t

__device__ __forceinline__ unsigned encf(float f) {
    unsigned u = __float_as_uint(f);
    return (u & 0x80000000u) ? ~u : (u | 0x80000000u);
}
__device__ __forceinline__ float decf(unsigned e) {
    unsigned u = (e & 0x80000000u) ? (e ^ 0x80000000u) : ~e;
    return __uint_as_float(u);
}
__device__ __forceinline__ uint32_t smem_u32(const void* p) {
    uint32_t a;
    asm("{ .reg .u64 t; cvta.to.shared.u64 t, %1; cvt.u32.u64 %0, t; }" : "=r"(a) : "l"(p));
    return a;
}
__device__ __forceinline__ void cpa16(uint32_t d, const void* s) {
    asm volatile("cp.async.cg.shared.global [%0], [%1], 16;" :: "r"(d), "l"(s) : "memory");
}
#define CP_COMMIT() asm volatile("cp.async.commit_group;" ::: "memory")
#define CP_WAIT(n)  asm volatile("cp.async.wait_group %0;" :: "n"(n) : "memory")

__device__ __forceinline__ void ldsm4(uint32_t& r0, uint32_t& r1, uint32_t& r2, uint32_t& r3,
                                      uint32_t addr) {
    asm volatile("ldmatrix.sync.aligned.m8n8.x4.shared.b16 {%0,%1,%2,%3}, [%4];"
                 : "=r"(r0), "=r"(r1), "=r"(r2), "=r"(r3) : "r"(addr));
}
__device__ __forceinline__ void mma16816(float& c0, float& c1, float& c2, float& c3,
                                         uint32_t a0, uint32_t a1, uint32_t a2, uint32_t a3,
                                         uint32_t b0, uint32_t b1) {
    asm volatile("mma.sync.aligned.m16n8k16.row.col.f32.f16.f16.f32 "
                 "{%0,%1,%2,%3},{%4,%5,%6,%7},{%8,%9},{%0,%1,%2,%3};"
                 : "+f"(c0), "+f"(c1), "+f"(c2), "+f"(c3)
                 : "r"(a0), "r"(a1), "r"(a2), "r"(a3), "r"(b0), "r"(b1));
}

// ---------------- normalize + fp16 copy + all init ----------------
__global__ void normalize_k(const float* __restrict__ emb) {
    int j = blockIdx.x, t = threadIdx.x;  // 64 threads, one float4 each
    float4 v = ((const float4*)(emb + (size_t)j * D_))[t];
    float ss = v.x * v.x + v.y * v.y + v.z * v.z + v.w * v.w;
    for (int o = 16; o; o >>= 1) ss += __shfl_xor_sync(0xffffffffu, ss, o);
    __shared__ float sred[2];
    if ((t & 31) == 0) sred[t >> 5] = ss;
    __syncthreads();
    float inv = 1.0f / fmaxf(sqrtf(sred[0] + sred[1]), 1e-12f);
    float4 o4 = make_float4(v.x * inv, v.y * inv, v.z * inv, v.w * inv);
    ((float4*)(g_normed + (size_t)j * D_))[t] = o4;
    __half2 h0 = __floats2half2_rn(o4.x, o4.y);
    __half2 h1 = __floats2half2_rn(o4.z, o4.w);
    ((__half2*)(g_nh + (size_t)j * D_ + t * 4))[0] = h0;
    ((__half2*)(g_nh + (size_t)j * D_ + t * 4))[1] = h1;
    if (t == 0) {
        g_hp[j] = 1e9f;
        g_validf[j] = 0.f;
        g_tE[j] = encf(-1e9f);
        if (j < NPID) g_cnt[j] = 0;
    }
}

// ---------------- pid buckets + column sentinels ----------------
__global__ void bucket_k(const int* __restrict__ labels, const int* __restrict__ pids) {
    int i = blockIdx.x * blockDim.x + threadIdx.x;
    if (i >= N_) return;
    int lab = labels[i], pid = pids[i];
    g_colsent[i] = (lab == 1) ? pid : -1;
    if (lab == 1) g_list[pid * CAP + atomicAdd(&g_cnt[pid], 1)] = i;
}

// ---------------- hardest positive: block per pid, smem-staged ----------------
__global__ void __launch_bounds__(256, 1)
hp_pid_k() {
    extern __shared__ float srow[];  // up to 64 rows x 256 floats
    int p = blockIdx.x;
    int n = g_cnt[p];
    if (n == 0) return;
    int ns = (n < 64) ? n : 64;
    for (int idx = threadIdx.x; idx < ns * 64; idx += 256) {
        int m = idx >> 6, q = idx & 63;
        ((float4*)srow)[m * 64 + q] =
            ((const float4*)(g_normed + (size_t)g_list[p * CAP + m] * D_))[q];
    }
    __syncthreads();
    int wid = threadIdx.x >> 5, lane = threadIdx.x & 31;
    float vf = (n >= 2) ? 1.f : 0.f;
    for (int a = wid; a < n; a += 8) {
        int i = g_list[p * CAP + a];
        const float* arow = (a < ns) ? (srow + a * D_) : (g_normed + (size_t)i * D_);
        float a8[8];
#pragma unroll
        for (int k = 0; k < 8; k++) a8[k] = arow[k * 32 + lane];
        float hp = 1e9f;
        for (int j = 0; j < n; j++) {
            if (j == a) continue;
            const float* br = (j < ns) ? (srow + j * D_)
                                       : (g_normed + (size_t)g_list[p * CAP + j] * D_);
            float s = 0.f;
#pragma unroll
            for (int k = 0; k < 8; k++) s = fmaf(a8[k], br[k * 32 + lane], s);
            for (int o = 16; o; o >>= 1) s += __shfl_xor_sync(0xffffffffu, s, o);
            hp = fminf(hp, s);
        }
        if (lane == 0) { g_hp[i] = hp; g_validf[i] = vf; }
    }
}

// ---------------- main: mma.sync fp16 GEMM + class-offset epilogue ----------------
__global__ void __launch_bounds__(256, 1)
main_k(const int* __restrict__ pids) {
    extern __shared__ char sm[];
    uint32_t sb = smem_u32(sm);
    const uint32_t A0 = sb, Bbuf0 = sb + 65536, Bbuf1 = sb + 131072;

    int tid = threadIdx.x, lane = tid & 31, wid = tid >> 5;
    int wr = (wid >> 2) * 64;
    int wc = (wid & 3) * 32;
    int row0 = blockIdx.x * 128;
    int col0 = blockIdx.y * 4096;

    {
        const __half* gs = g_nh + (size_t)row0 * D_;
#pragma unroll
        for (int i = 0; i < 16; i++) {
            int id = tid + i * 256, r = id >> 5, c = id & 31;
            cpa16(A0 + r * 512 + ((c ^ (r & 7)) << 4), gs + r * 256 + c * 8);
        }
        CP_COMMIT();
    }
    {
        const __half* gs = g_nh + (size_t)col0 * D_;
#pragma unroll
        for (int i = 0; i < 16; i++) {
            int id = tid + i * 256, r = id >> 5, c = id & 31;
            cpa16(Bbuf0 + r * 512 + ((c ^ (r & 7)) << 4), gs + r * 256 + c * 8);
        }
        CP_COMMIT();
    }

    int gid = lane >> 2, tig = lane & 3;
    float hp_s[8], hpm_s[8], run[8];
    int pid_s[8];
#pragma unroll
    for (int m = 0; m < 4; m++) {
        int rA = row0 + wr + m * 16 + gid;
        hp_s[2 * m] = g_hp[rA];         pid_s[2 * m] = pids[rA];
        hp_s[2 * m + 1] = g_hp[rA + 8]; pid_s[2 * m + 1] = pids[rA + 8];
    }
#pragma unroll
    for (int s = 0; s < 8; s++) { hpm_s[s] = hp_s[s] - 0.5f; run[s] = -1e9f; }

    int arow = lane & 15;
    int kha = lane >> 4;
    int brow = ((lane >> 4) & 1) * 8 + (lane & 7);
    int khb = (lane >> 3) & 1;
    int xr = lane & 7;
    uint32_t aAddr[4];
#pragma unroll
    for (int m = 0; m < 4; m++) aAddr[m] = A0 + (wr + m * 16 + arow) * 512;

    for (int t = 0; t < NTILE; t++) {
        uint32_t Bc = (t & 1) ? Bbuf1 : Bbuf0;
        if (t + 1 < NTILE) {
            uint32_t Bn = (t & 1) ? Bbuf0 : Bbuf1;
            const __half* gs = g_nh + (size_t)(col0 + (t + 1) * 128) * D_;
#pragma unroll
            for (int i = 0; i < 16; i++) {
                int id = tid + i * 256, r = id >> 5, c = id & 31;
                cpa16(Bn + r * 512 + ((c ^ (r & 7)) << 4), gs + r * 256 + c * 8);
            }
            CP_COMMIT();
            CP_WAIT(1);
        } else {
            CP_WAIT(0);
        }
        __syncthreads();

        uint32_t bAddr0 = Bc + (wc + brow) * 512;
        uint32_t bAddr1 = Bc + (wc + 16 + brow) * 512;

        float acc[4][4][4];
#pragma unroll
        for (int m = 0; m < 4; m++)
#pragma unroll
            for (int n = 0; n < 4; n++)
#pragma unroll
                for (int q = 0; q < 4; q++) acc[m][n][q] = 0.f;

#pragma unroll
        for (int ks = 0; ks < 16; ks++) {
            uint32_t aoff = (uint32_t)(((ks * 2 + kha) ^ xr) << 4);
            uint32_t boff = (uint32_t)(((ks * 2 + khb) ^ xr) << 4);
            uint32_t a[4][4], b[2][4];
#pragma unroll
            for (int m = 0; m < 4; m++)
                ldsm4(a[m][0], a[m][1], a[m][2], a[m][3], aAddr[m] + aoff);
            ldsm4(b[0][0], b[0][1], b[0][2], b[0][3], bAddr0 + boff);
            ldsm4(b[1][0], b[1][1], b[1][2], b[1][3], bAddr1 + boff);
#pragma unroll
            for (int m = 0; m < 4; m++) {
                mma16816(acc[m][0][0], acc[m][0][1], acc[m][0][2], acc[m][0][3],
                         a[m][0], a[m][1], a[m][2], a[m][3], b[0][0], b[0][1]);
                mma16816(acc[m][1][0], acc[m][1][1], acc[m][1][2], acc[m][1][3],
                         a[m][0], a[m][1], a[m][2], a[m][3], b[0][2], b[0][3]);
                mma16816(acc[m][2][0], acc[m][2][1], acc[m][2][2], acc[m][2][3],
                         a[m][0], a[m][1], a[m][2], a[m][3], b[1][0], b[1][1]);
                mma16816(acc[m][3][0], acc[m][3][1], acc[m][3][2], acc[m][3][3],
                         a[m][0], a[m][1], a[m][2], a[m][3], b[1][2], b[1][3]);
            }
        }
        __syncthreads();

        // fold tile: t = v + (semi?8 : cand?4 : 0), masked, single running max
        int cb = col0 + t * 128 + wc;
#pragma unroll
        for (int n = 0; n < 4; n++) {
            int c0 = cb + n * 8 + tig * 2;
            int s0 = __ldg(&g_colsent[c0]);
            int s1 = __ldg(&g_colsent[c0 + 1]);
#pragma unroll
            for (int m = 0; m < 4; m++) {
#pragma unroll
                for (int h = 0; h < 2; h++) {
                    int slot = 2 * m + h;
                    float hpv = hp_s[slot], hpl = hpm_s[slot];
                    int mp = pid_s[slot];
                    float v0 = acc[m][n][h * 2 + 0];
                    float v1 = acc[m][n][h * 2 + 1];
                    float add0 = (v0 > hpv) ? 4.f : ((v0 > hpl && v0 < hpv) ? 8.f : 0.f);
                    float add1 = (v1 > hpv) ? 4.f : ((v1 > hpl && v1 < hpv) ? 8.f : 0.f);
                    float t0 = (s0 == mp) ? -1e9f : (v0 + add0);
                    float t1 = (s1 == mp) ? -1e9f : (v1 + add1);
                    run[slot] = fmaxf(run[slot], fmaxf(t0, t1));
                }
            }
        }
    }

#pragma unroll
    for (int s = 0; s < 8; s++)
        for (int o = 1; o < 4; o <<= 1)
            run[s] = fmaxf(run[s], __shfl_xor_sync(0xffffffffu, run[s], o));
    if (tig == 0) {
#pragma unroll
        for (int m = 0; m < 4; m++) {
            int r = row0 + wr + m * 16 + gid;
            atomicMax(&g_tE[r], encf(run[2 * m]));
            atomicMax(&g_tE[r + 8], encf(run[2 * m + 1]));
        }
    }
}

// ---------------- final reduce (fp32, warp-pairwise) ----------------
__global__ void finish_k(float* __restrict__ out) {
    float s = 0.f, c = 0.f;
    for (int i = threadIdx.x; i < N_; i += blockDim.x) {
        if (g_validf[i] > 0.f) {
            float hp = g_hp[i];
            float t = decf(g_tE[i]);
            float hn = (t >= 6.f) ? (t - 8.f) : ((t >= 2.f) ? (t - 4.f) : t);
            float base = fmaxf(hn - hp + 0.5f, 0.f);
            float w = (hp < 0.6f || hn > 0.3f) ? 2.0f : 1.0f;
            s += base * w + 0.5f * (1.0f - hp) + 0.5f * fmaxf(hn + 0.2f, 0.f);
            c += 1.f;
        }
    }
    __shared__ float rs[32], rc[32];
    for (int o = 16; o; o >>= 1) {
        s += __shfl_xor_sync(0xffffffffu, s, o);
        c += __shfl_xor_sync(0xffffffffu, c, o);
    }
    int wid = threadIdx.x >> 5, lane = threadIdx.x & 31;
    if (lane == 0) { rs[wid] = s; rc[wid] = c; }
    __syncthreads();
    int nw = (blockDim.x + 31) >> 5;
    if (wid == 0) {
        float vs = lane < nw ? rs[lane] : 0.f;
        float vc = lane < nw ? rc[lane] : 0.f;
        for (int o = 16; o; o >>= 1) {
            vs += __shfl_xor_sync(0xffffffffu, vs, o);
            vc += __shfl_xor_sync(0xffffffffu, vc, o);
        }
        if (lane == 0) out[0] = (vc > 0.f) ? (vs / vc) : 0.f;
    }
}

// ---------------- launcher ----------------
extern "C" void kernel_launch(void* const* d_in, const int* in_sizes, int n_in,
                              void* d_out, int out_size) {
    const float* emb = (const float*)d_in[0];
    const int* labels = (const int*)d_in[1];
    const int* pids = (const int*)d_in[2];
    float* out = (float*)d_out;

    cudaFuncSetAttribute(main_k, cudaFuncAttributeMaxDynamicSharedMemorySize, 196608);
    cudaFuncSetAttribute(hp_pid_k, cudaFuncAttributeMaxDynamicSharedMemorySize, 65536);

    normalize_k<<<N_, 64>>>(emb);
    bucket_k<<<N_ / 256, 256>>>(labels, pids);
    hp_pid_k<<<NPID, 256, 65536>>>();
    main_k<<<dim3(64, 2), 256, 196608>>>(pids);
    finish_k<<<1, 1024>>>(out);
}

// round 6
// speedup vs baseline: 11.2975x; 1.0574x over previous
#include <cuda_runtime.h>
#include <cuda_fp16.h>
#include <cstdint>
#include <math.h>

#define N_    8192
#define D_    256
#define NPID  256
#define CAP   8192
#define NTILE 32

__device__ float    g_normed[N_ * D_];
__device__ __half   g_nh[N_ * D_];
__device__ float    g_hp[N_];
__device__ float    g_validf[N_];
__device__ int      g_colsent[N_];
__device__ int      g_cnt[NPID];
__device__ int      g_list[NPID * CAP];
__device__ unsigned g_aE[N_];   // encoded max over masked negatives (all)
__device__ unsigned g_bE[N_];   // encoded max over masked negatives with v < hp

__device__ __forceinline__ unsigned encf(float f) {
    unsigned u = __float_as_uint(f);
    return (u & 0x80000000u) ? ~u : (u | 0x80000000u);
}
__device__ __forceinline__ float decf(unsigned e) {
    unsigned u = (e & 0x80000000u) ? (e ^ 0x80000000u) : ~e;
    return __uint_as_float(u);
}
__device__ __forceinline__ uint32_t smem_u32(const void* p) {
    uint32_t a;
    asm("{ .reg .u64 t; cvta.to.shared.u64 t, %1; cvt.u32.u64 %0, t; }" : "=r"(a) : "l"(p));
    return a;
}
__device__ __forceinline__ void cpa16(uint32_t d, const void* s) {
    asm volatile("cp.async.cg.shared.global [%0], [%1], 16;" :: "r"(d), "l"(s) : "memory");
}
#define CP_COMMIT() asm volatile("cp.async.commit_group;" ::: "memory")
#define CP_WAIT(n)  asm volatile("cp.async.wait_group %0;" :: "n"(n) : "memory")

__device__ __forceinline__ void ldsm4(uint32_t& r0, uint32_t& r1, uint32_t& r2, uint32_t& r3,
                                      uint32_t addr) {
    asm volatile("ldmatrix.sync.aligned.m8n8.x4.shared.b16 {%0,%1,%2,%3}, [%4];"
                 : "=r"(r0), "=r"(r1), "=r"(r2), "=r"(r3) : "r"(addr));
}
__device__ __forceinline__ void mma16816(float& c0, float& c1, float& c2, float& c3,
                                         uint32_t a0, uint32_t a1, uint32_t a2, uint32_t a3,
                                         uint32_t b0, uint32_t b1) {
    asm volatile("mma.sync.aligned.m16n8k16.row.col.f32.f16.f16.f32 "
                 "{%0,%1,%2,%3},{%4,%5,%6,%7},{%8,%9},{%0,%1,%2,%3};"
                 : "+f"(c0), "+f"(c1), "+f"(c2), "+f"(c3)
                 : "r"(a0), "r"(a1), "r"(a2), "r"(a3), "r"(b0), "r"(b1));
}

// ---------------- normalize + fp16 copy + all init ----------------
__global__ void normalize_k(const float* __restrict__ emb) {
    int j = blockIdx.x, t = threadIdx.x;  // 64 threads, one float4 each
    float4 v = ((const float4*)(emb + (size_t)j * D_))[t];
    float ss = v.x * v.x + v.y * v.y + v.z * v.z + v.w * v.w;
    for (int o = 16; o; o >>= 1) ss += __shfl_xor_sync(0xffffffffu, ss, o);
    __shared__ float sred[2];
    if ((t & 31) == 0) sred[t >> 5] = ss;
    __syncthreads();
    float inv = 1.0f / fmaxf(sqrtf(sred[0] + sred[1]), 1e-12f);
    float4 o4 = make_float4(v.x * inv, v.y * inv, v.z * inv, v.w * inv);
    ((float4*)(g_normed + (size_t)j * D_))[t] = o4;
    __half2 h0 = __floats2half2_rn(o4.x, o4.y);
    __half2 h1 = __floats2half2_rn(o4.z, o4.w);
    ((__half2*)(g_nh + (size_t)j * D_ + t * 4))[0] = h0;
    ((__half2*)(g_nh + (size_t)j * D_ + t * 4))[1] = h1;
    if (t == 0) {
        g_hp[j] = 1e9f;
        g_validf[j] = 0.f;
        unsigned e = encf(-1e9f);
        g_aE[j] = e;
        g_bE[j] = e;
        if (j < NPID) g_cnt[j] = 0;
    }
}

// ---------------- pid buckets + column sentinels ----------------
__global__ void bucket_k(const int* __restrict__ labels, const int* __restrict__ pids) {
    int i = blockIdx.x * blockDim.x + threadIdx.x;
    if (i >= N_) return;
    int lab = labels[i], pid = pids[i];
    g_colsent[i] = (lab == 1) ? pid : -1;
    if (lab == 1) g_list[pid * CAP + atomicAdd(&g_cnt[pid], 1)] = i;
}

// ---------------- hardest positive: block per pid, smem-staged ----------------
__global__ void __launch_bounds__(256, 1)
hp_pid_k() {
    extern __shared__ float srow[];  // up to 64 rows x 256 floats
    int p = blockIdx.x;
    int n = g_cnt[p];
    if (n == 0) return;
    int ns = (n < 64) ? n : 64;
    for (int idx = threadIdx.x; idx < ns * 64; idx += 256) {
        int m = idx >> 6, q = idx & 63;
        ((float4*)srow)[m * 64 + q] =
            ((const float4*)(g_normed + (size_t)g_list[p * CAP + m] * D_))[q];
    }
    __syncthreads();
    int wid = threadIdx.x >> 5, lane = threadIdx.x & 31;
    float vf = (n >= 2) ? 1.f : 0.f;
    for (int a = wid; a < n; a += 8) {
        int i = g_list[p * CAP + a];
        const float* arow = (a < ns) ? (srow + a * D_) : (g_normed + (size_t)i * D_);
        float a8[8];
#pragma unroll
        for (int k = 0; k < 8; k++) a8[k] = arow[k * 32 + lane];
        float hp = 1e9f;
        for (int j = 0; j < n; j++) {
            if (j == a) continue;
            const float* br = (j < ns) ? (srow + j * D_)
                                       : (g_normed + (size_t)g_list[p * CAP + j] * D_);
            float s = 0.f;
#pragma unroll
            for (int k = 0; k < 8; k++) s = fmaf(a8[k], br[k * 32 + lane], s);
            for (int o = 16; o; o >>= 1) s += __shfl_xor_sync(0xffffffffu, s, o);
            hp = fminf(hp, s);
        }
        if (lane == 0) { g_hp[i] = hp; g_validf[i] = vf; }
    }
}

// ---------------- main: mma.sync fp16 GEMM + two-max epilogue ----------------
__global__ void __launch_bounds__(256, 1)
main_k(const int* __restrict__ pids) {
    extern __shared__ char sm[];
    uint32_t sb = smem_u32(sm);
    const uint32_t A0 = sb, Bbuf0 = sb + 65536, Bbuf1 = sb + 131072;

    int tid = threadIdx.x, lane = tid & 31, wid = tid >> 5;
    int wr = (wid >> 2) * 64;
    int wc = (wid & 3) * 32;
    int row0 = blockIdx.x * 128;
    int col0 = blockIdx.y * 4096;

    {
        const __half* gs = g_nh + (size_t)row0 * D_;
#pragma unroll
        for (int i = 0; i < 16; i++) {
            int id = tid + i * 256, r = id >> 5, c = id & 31;
            cpa16(A0 + r * 512 + ((c ^ (r & 7)) << 4), gs + r * 256 + c * 8);
        }
        CP_COMMIT();
    }
    {
        const __half* gs = g_nh + (size_t)col0 * D_;
#pragma unroll
        for (int i = 0; i < 16; i++) {
            int id = tid + i * 256, r = id >> 5, c = id & 31;
            cpa16(Bbuf0 + r * 512 + ((c ^ (r & 7)) << 4), gs + r * 256 + c * 8);
        }
        CP_COMMIT();
    }

    int gid = lane >> 2, tig = lane & 3;
    float hp_s[8], mA[8], mB[8];
    int pid_s[8];
#pragma unroll
    for (int m = 0; m < 4; m++) {
        int rA = row0 + wr + m * 16 + gid;
        hp_s[2 * m] = g_hp[rA];         pid_s[2 * m] = pids[rA];
        hp_s[2 * m + 1] = g_hp[rA + 8]; pid_s[2 * m + 1] = pids[rA + 8];
    }
#pragma unroll
    for (int s = 0; s < 8; s++) { mA[s] = -1e9f; mB[s] = -1e9f; }

    int arow = lane & 15;
    int kha = lane >> 4;
    int brow = ((lane >> 4) & 1) * 8 + (lane & 7);
    int khb = (lane >> 3) & 1;
    int xr = lane & 7;
    uint32_t aAddr[4];
#pragma unroll
    for (int m = 0; m < 4; m++) aAddr[m] = A0 + (wr + m * 16 + arow) * 512;

    for (int t = 0; t < NTILE; t++) {
        uint32_t Bc = (t & 1) ? Bbuf1 : Bbuf0;
        if (t + 1 < NTILE) {
            uint32_t Bn = (t & 1) ? Bbuf0 : Bbuf1;
            const __half* gs = g_nh + (size_t)(col0 + (t + 1) * 128) * D_;
#pragma unroll
            for (int i = 0; i < 16; i++) {
                int id = tid + i * 256, r = id >> 5, c = id & 31;
                cpa16(Bn + r * 512 + ((c ^ (r & 7)) << 4), gs + r * 256 + c * 8);
            }
            CP_COMMIT();
            CP_WAIT(1);
        } else {
            CP_WAIT(0);
        }
        __syncthreads();

        uint32_t bAddr0 = Bc + (wc + brow) * 512;
        uint32_t bAddr1 = Bc + (wc + 16 + brow) * 512;

        float acc[4][4][4];
#pragma unroll
        for (int m = 0; m < 4; m++)
#pragma unroll
            for (int n = 0; n < 4; n++)
#pragma unroll
                for (int q = 0; q < 4; q++) acc[m][n][q] = 0.f;

#pragma unroll
        for (int ks = 0; ks < 16; ks++) {
            uint32_t aoff = (uint32_t)(((ks * 2 + kha) ^ xr) << 4);
            uint32_t boff = (uint32_t)(((ks * 2 + khb) ^ xr) << 4);
            uint32_t a[4][4], b[2][4];
#pragma unroll
            for (int m = 0; m < 4; m++)
                ldsm4(a[m][0], a[m][1], a[m][2], a[m][3], aAddr[m] + aoff);
            ldsm4(b[0][0], b[0][1], b[0][2], b[0][3], bAddr0 + boff);
            ldsm4(b[1][0], b[1][1], b[1][2], b[1][3], bAddr1 + boff);
#pragma unroll
            for (int m = 0; m < 4; m++) {
                mma16816(acc[m][0][0], acc[m][0][1], acc[m][0][2], acc[m][0][3],
                         a[m][0], a[m][1], a[m][2], a[m][3], b[0][0], b[0][1]);
                mma16816(acc[m][1][0], acc[m][1][1], acc[m][1][2], acc[m][1][3],
                         a[m][0], a[m][1], a[m][2], a[m][3], b[0][2], b[0][3]);
                mma16816(acc[m][2][0], acc[m][2][1], acc[m][2][2], acc[m][2][3],
                         a[m][0], a[m][1], a[m][2], a[m][3], b[1][0], b[1][1]);
                mma16816(acc[m][3][0], acc[m][3][1], acc[m][3][2], acc[m][3][3],
                         a[m][0], a[m][1], a[m][2], a[m][3], b[1][2], b[1][3]);
            }
        }

        // epilogue BEFORE the barrier: fold tile into (maxAll, maxBelow)
        int cb = col0 + t * 128 + wc;
#pragma unroll
        for (int n = 0; n < 4; n++) {
            int c0 = cb + n * 8 + tig * 2;
            int s0 = __ldg(&g_colsent[c0]);
            int s1 = __ldg(&g_colsent[c0 + 1]);
#pragma unroll
            for (int m = 0; m < 4; m++) {
#pragma unroll
                for (int h = 0; h < 2; h++) {
                    int slot = 2 * m + h;
                    float hpv = hp_s[slot];
                    int mp = pid_s[slot];
                    float v0 = acc[m][n][h * 2 + 0];
                    float v1 = acc[m][n][h * 2 + 1];
                    bool k0 = (s0 == mp), k1 = (s1 == mp);
                    float a0 = k0 ? -1e9f : v0;
                    float a1 = k1 ? -1e9f : v1;
                    mA[slot] = fmaxf(mA[slot], fmaxf(a0, a1));
                    float b0 = (k0 || v0 >= hpv) ? -1e9f : v0;
                    float b1 = (k1 || v1 >= hpv) ? -1e9f : v1;
                    mB[slot] = fmaxf(mB[slot], fmaxf(b0, b1));
                }
            }
        }
        __syncthreads();  // guards buffer reuse by prefetch(t+2)
    }

#pragma unroll
    for (int s = 0; s < 8; s++)
        for (int o = 1; o < 4; o <<= 1) {
            mA[s] = fmaxf(mA[s], __shfl_xor_sync(0xffffffffu, mA[s], o));
            mB[s] = fmaxf(mB[s], __shfl_xor_sync(0xffffffffu, mB[s], o));
        }
    if (tig == 0) {
#pragma unroll
        for (int m = 0; m < 4; m++) {
            int r = row0 + wr + m * 16 + gid;
            atomicMax(&g_aE[r], encf(mA[2 * m]));
            atomicMax(&g_bE[r], encf(mB[2 * m]));
            atomicMax(&g_aE[r + 8], encf(mA[2 * m + 1]));
            atomicMax(&g_bE[r + 8], encf(mB[2 * m + 1]));
        }
    }
}

// ---------------- final reduce ----------------
__global__ void finish_k(float* __restrict__ out) {
    float s = 0.f, c = 0.f;
    for (int i = threadIdx.x; i < N_; i += blockDim.x) {
        if (g_validf[i] > 0.f) {
            float hp = g_hp[i];
            float maxA = decf(g_aE[i]);
            float maxB = decf(g_bE[i]);
            // semi exists iff maxBelow in (hp-0.5, hp); else cand-or-all == maxA
            float hn = (maxB > hp - 0.5f) ? maxB : maxA;
            float base = fmaxf(hn - hp + 0.5f, 0.f);
            float w = (hp < 0.6f || hn > 0.3f) ? 2.0f : 1.0f;
            s += base * w + 0.5f * (1.0f - hp) + 0.5f * fmaxf(hn + 0.2f, 0.f);
            c += 1.f;
        }
    }
    __shared__ float rs[32], rc[32];
    for (int o = 16; o; o >>= 1) {
        s += __shfl_xor_sync(0xffffffffu, s, o);
        c += __shfl_xor_sync(0xffffffffu, c, o);
    }
    int wid = threadIdx.x >> 5, lane = threadIdx.x & 31;
    if (lane == 0) { rs[wid] = s; rc[wid] = c; }
    __syncthreads();
    int nw = (blockDim.x + 31) >> 5;
    if (wid == 0) {
        float vs = lane < nw ? rs[lane] : 0.f;
        float vc = lane < nw ? rc[lane] : 0.f;
        for (int o = 16; o; o >>= 1) {
            vs += __shfl_xor_sync(0xffffffffu, vs, o);
            vc += __shfl_xor_sync(0xffffffffu, vc, o);
        }
        if (lane == 0) out[0] = (vc > 0.f) ? (vs / vc) : 0.f;
    }
}

// ---------------- launcher ----------------
extern "C" void kernel_launch(void* const* d_in, const int* in_sizes, int n_in,
                              void* d_out, int out_size) {
    const float* emb = (const float*)d_in[0];
    const int* labels = (const int*)d_in[1];
    const int* pids = (const int*)d_in[2];
    float* out = (float*)d_out;

    cudaFuncSetAttribute(main_k, cudaFuncAttributeMaxDynamicSharedMemorySize, 196608);
    cudaFuncSetAttribute(hp_pid_k, cudaFuncAttributeMaxDynamicSharedMemorySize, 65536);

    normalize_k<<<N_, 64>>>(emb);
    bucket_k<<<N_ / 256, 256>>>(labels, pids);
    hp_pid_k<<<NPID, 256, 65536>>>();
    main_k<<<dim3(64, 2), 256, 196608>>>(pids);
    finish_k<<<1, 1024>>>(out);
}